// round 1
// baseline (speedup 1.0000x reference)
#include <cuda_runtime.h>
#include <math.h>

#define BB 32
#define NN 16384
#define DD 64
#define SS 7
#define HH 128
#define TILE 128
#define TPB_ATTN 128
#define TILES_PER_B (NN / TILE)   // 128

__device__ __align__(16) float g_P[DD*DD];
__device__ __align__(16) float g_slots[BB*SS*DD];
__device__ __align__(16) float g_h0[BB*DD];
__device__ __align__(16) float g_qp[BB*SS*DD];
__device__ __align__(16) float g_U[BB*SS*DD];
__device__ float g_Z[BB*SS];

// ---------------------------------------------------------------------------
// k_setup: blocks 0..31 -> slots/h0 init + zero U,Z for batch b.
//          block 32     -> P[d'][d] = sum_e Wq[e,d'] * Wk[e,d]
// ---------------------------------------------------------------------------
__global__ void k_setup(const float* __restrict__ mu, const float* __restrict__ lsig,
                        const float* __restrict__ nslots, const float* __restrict__ nh,
                        const float* __restrict__ Wq, const float* __restrict__ Wk) {
    int blk = blockIdx.x;
    int tid = threadIdx.x;
    if (blk < BB) {
        int b = blk;
        for (int i = tid; i < SS*DD; i += blockDim.x) {
            int d = i & (DD-1);
            float sg = expf(lsig[d]);
            g_slots[b*SS*DD + i] = mu[d] + sg * nslots[b*SS*DD + i];
            g_U[b*SS*DD + i] = 0.f;
        }
        for (int d = tid; d < DD; d += blockDim.x) {
            float sg = expf(lsig[d]);
            g_h0[b*DD + d] = mu[d] + sg * nh[b*DD + d];
        }
        if (tid < SS) g_Z[b*SS + tid] = 0.f;
    } else {
        for (int i = tid; i < DD*DD; i += blockDim.x) {
            int dp = i >> 6, d = i & 63;
            float acc = 0.f;
            for (int e = 0; e < DD; e++) acc += Wq[e*DD+dp] * Wk[e*DD+d];
            g_P[i] = acc;
        }
    }
}

// ---------------------------------------------------------------------------
// k_qp0: q'[b,s,:] = scale * LN_slots(slots[b,s]) @ P    (iteration-0 q')
// ---------------------------------------------------------------------------
__global__ void k_qp0(const float* __restrict__ lsg, const float* __restrict__ lsb) {
    int b = blockIdx.x, tid = threadIdx.x;
    __shared__ float sl[SS*DD], sn[SS*DD], m7[SS], r7[SS];
    for (int i = tid; i < SS*DD; i += blockDim.x) sl[i] = g_slots[b*SS*DD+i];
    __syncthreads();
    if (tid < SS) {
        float sm = 0.f, sq = 0.f;
        for (int d = 0; d < DD; d++) { float v = sl[tid*DD+d]; sm += v; sq += v*v; }
        float m = sm * (1.f/DD);
        m7[tid] = m;
        r7[tid] = rsqrtf(sq*(1.f/DD) - m*m + 1e-5f);
    }
    __syncthreads();
    for (int i = tid; i < SS*DD; i += blockDim.x) {
        int s = i >> 6, d = i & 63;
        sn[i] = (sl[i]-m7[s])*r7[s]*lsg[d] + lsb[d];
    }
    __syncthreads();
    for (int o = tid; o < SS*DD; o += blockDim.x) {
        int s = o >> 6, d = o & 63;
        float acc = 0.f;
        for (int dp = 0; dp < DD; dp++) acc += sn[s*DD+dp] * g_P[dp*DD+d];
        g_qp[b*SS*DD+o] = 0.125f * acc;   // scale = D^-0.5 = 1/8
    }
}

// ---------------------------------------------------------------------------
// k_attn: the fused big pass. Per row: LN(x) -> 7 logits vs q' -> softmax+eps
//         -> accumulate U[s][d] += p_s * xn[d] and Z[s] += p_s (tile-local,
//         then global fp32 atomics).
// ---------------------------------------------------------------------------
__global__ __launch_bounds__(TPB_ATTN, 4)
void k_attn(const float* __restrict__ x_in,
            const float* __restrict__ lg, const float* __restrict__ lb) {
    __shared__ float4 s_xn[TILE][DD/4];          // 32 KB, normalized rows
    __shared__ float  s_p[SS][TILE];             // attention probs (+eps)
    __shared__ float4 s_qp[SS][DD/4];
    __shared__ float  s_g[DD], s_b[DD];

    int b   = blockIdx.x >> 7;                   // TILES_PER_B == 128
    int rb  = (blockIdx.x & (TILES_PER_B-1)) * TILE;
    int tid = threadIdx.x;

    for (int i = tid; i < SS*DD/4; i += TPB_ATTN)
        ((float4*)s_qp)[i] = ((const float4*)(g_qp + b*SS*DD))[i];
    if (tid < DD) { s_g[tid] = lg[tid]; s_b[tid] = lb[tid]; }
    __syncthreads();

    // ---- phase 1: one row per thread, row held in 16 x float4 registers ----
    {
        const float4* xp = (const float4*)(x_in + ((long)b*NN + rb + tid)*DD);
        float4 x[16];
#pragma unroll
        for (int j = 0; j < 16; j++) x[j] = xp[j];
        float sm = 0.f, sq = 0.f;
#pragma unroll
        for (int j = 0; j < 16; j++) {
            sm += x[j].x + x[j].y + x[j].z + x[j].w;
            sq += x[j].x*x[j].x + x[j].y*x[j].y + x[j].z*x[j].z + x[j].w*x[j].w;
        }
        float m = sm * (1.f/DD);
        float rstd = rsqrtf(sq*(1.f/DD) - m*m + 1e-5f);
#pragma unroll
        for (int j = 0; j < 16; j++) {
            x[j].x = (x[j].x - m)*rstd*s_g[4*j+0] + s_b[4*j+0];
            x[j].y = (x[j].y - m)*rstd*s_g[4*j+1] + s_b[4*j+1];
            x[j].z = (x[j].z - m)*rstd*s_g[4*j+2] + s_b[4*j+2];
            x[j].w = (x[j].w - m)*rstd*s_g[4*j+3] + s_b[4*j+3];
        }
        float l[SS];
#pragma unroll
        for (int s = 0; s < SS; s++) {
            float acc = 0.f;
#pragma unroll
            for (int j = 0; j < 16; j++) {
                float4 q = s_qp[s][j];
                acc += x[j].x*q.x + x[j].y*q.y + x[j].z*q.z + x[j].w*q.w;
            }
            l[s] = acc;
        }
        float mx = l[0];
#pragma unroll
        for (int s = 1; s < SS; s++) mx = fmaxf(mx, l[s]);
        float es[SS], se = 0.f;
#pragma unroll
        for (int s = 0; s < SS; s++) { es[s] = __expf(l[s]-mx); se += es[s]; }
        float inv = 1.f/se;
#pragma unroll
        for (int s = 0; s < SS; s++) s_p[s][tid] = es[s]*inv + 1e-8f;
#pragma unroll
        for (int j = 0; j < 16; j++) s_xn[tid][j] = x[j];
    }
    __syncthreads();

    // ---- phase 2: outer-product accumulation with register accumulators ----
    if (tid < SS*16) {                           // 112 threads: (s, d-quad)
        int s = tid >> 4, dq = tid & 15;
        float4 acc = make_float4(0.f,0.f,0.f,0.f);
#pragma unroll 4
        for (int r = 0; r < TILE; r++) {
            float  pv = s_p[s][r];
            float4 xv = s_xn[r][dq];
            acc.x += pv*xv.x; acc.y += pv*xv.y; acc.z += pv*xv.z; acc.w += pv*xv.w;
        }
        float* up = g_U + (b*SS + s)*DD + dq*4;
        atomicAdd(up+0, acc.x); atomicAdd(up+1, acc.y);
        atomicAdd(up+2, acc.z); atomicAdd(up+3, acc.w);
    } else if (tid < SS*16 + SS) {               // 7 threads: Z partials
        int s = tid - SS*16;
        float z = 0.f;
#pragma unroll 4
        for (int r = 0; r < TILE; r++) z += s_p[s][r];
        atomicAdd(&g_Z[b*SS+s], z);
    }
}

// ---------------------------------------------------------------------------
// k_update: updates = (U @ Wv^T)/Z -> GRU over S -> MLP residual
//           -> write slots (+d_out) -> next iteration's q' + zero U,Z.
// ---------------------------------------------------------------------------
__global__ __launch_bounds__(256)
void k_update(const float* __restrict__ Wv,
              const float* __restrict__ w_ih, const float* __restrict__ w_hh,
              const float* __restrict__ b_ih, const float* __restrict__ b_hh,
              const float* __restrict__ w1, const float* __restrict__ b1,
              const float* __restrict__ w2, const float* __restrict__ b2,
              const float* __restrict__ lsg, const float* __restrict__ lsb,
              const float* __restrict__ lmg, const float* __restrict__ lmb,
              float* __restrict__ dout, int last) {
    int b = blockIdx.x, tid = threadIdx.x;
    __shared__ float sU[SS*DD], sZ[SS], upd[SS*DD];
    __shared__ float h[DD], gi[3][DD], gh[3][DD];
    __shared__ float sl[SS*DD], hid[SS*HH], m7[SS], r7[SS], xb[SS*DD];

    for (int i = tid; i < SS*DD; i += 256) sU[i] = g_U[b*SS*DD+i];
    if (tid < SS) sZ[tid] = g_Z[b*SS+tid];
    if (tid < DD) h[tid] = g_h0[b*DD+tid];
    __syncthreads();

    // updates[s][e] = sum_d U[s][d] * Wv[e][d] / Z[s]
    for (int o = tid; o < SS*DD; o += 256) {
        int s = o >> 6, e = o & 63;
        float acc = 0.f;
        const float* w = Wv + e*DD;
        for (int d = 0; d < DD; d++) acc += sU[s*DD+d] * w[d];
        upd[o] = acc / sZ[s];
    }
    __syncthreads();

    // GRU over slot axis (sequential, fresh h0), gate order r,z,n
    for (int s = 0; s < SS; s++) {
        if (tid < 3*DD) {
            int g = tid >> 6, d = tid & 63;
            float a = b_ih[g*DD+d], c = b_hh[g*DD+d];
            const float* wi = w_ih + (g*DD+d)*DD;
            const float* wh = w_hh + (g*DD+d)*DD;
            for (int e = 0; e < DD; e++) { a += upd[s*DD+e]*wi[e]; c += h[e]*wh[e]; }
            gi[g][d] = a; gh[g][d] = c;
        }
        __syncthreads();
        float hn = 0.f;
        if (tid < DD) {
            float r = 1.f/(1.f + expf(-(gi[0][tid]+gh[0][tid])));
            float z = 1.f/(1.f + expf(-(gi[1][tid]+gh[1][tid])));
            float n = tanhf(gi[2][tid] + r*gh[2][tid]);
            hn = (1.f-z)*n + z*h[tid];
        }
        __syncthreads();
        if (tid < DD) { h[tid] = hn; sl[s*DD+tid] = hn; }
        __syncthreads();
    }

    // MLP: slots += relu(LN_mlp(slots) @ w1^T + b1) @ w2^T + b2
    if (tid < SS) {
        float sm = 0.f, sq = 0.f;
        for (int d = 0; d < DD; d++) { float v = sl[tid*DD+d]; sm += v; sq += v*v; }
        float m = sm*(1.f/DD);
        m7[tid] = m; r7[tid] = rsqrtf(sq*(1.f/DD) - m*m + 1e-5f);
    }
    __syncthreads();
    for (int i = tid; i < SS*DD; i += 256) {
        int s = i >> 6, d = i & 63;
        xb[i] = (sl[i]-m7[s])*r7[s]*lmg[d] + lmb[d];
    }
    __syncthreads();
    for (int o = tid; o < SS*HH; o += 256) {
        int s = o >> 7, hc = o & 127;
        float acc = b1[hc];
        const float* w = w1 + hc*DD;
        for (int d = 0; d < DD; d++) acc += xb[s*DD+d]*w[d];
        hid[o] = fmaxf(acc, 0.f);
    }
    __syncthreads();
    for (int o = tid; o < SS*DD; o += 256) {
        int s = o >> 6, d = o & 63;
        float acc = b2[d];
        const float* w = w2 + d*HH;
        for (int k = 0; k < HH; k++) acc += hid[s*HH+k]*w[k];
        float v = sl[o] + acc;
        upd[o] = v;                      // reuse as new-slots buffer
        g_slots[b*SS*DD+o] = v;
        dout[b*SS*DD+o] = v;
    }
    __syncthreads();

    if (!last) {
        // next iteration's q' = scale * LN_slots(new slots) @ P ; zero U,Z
        if (tid < SS) {
            float sm = 0.f, sq = 0.f;
            for (int d = 0; d < DD; d++) { float v = upd[tid*DD+d]; sm += v; sq += v*v; }
            float m = sm*(1.f/DD);
            m7[tid] = m; r7[tid] = rsqrtf(sq*(1.f/DD) - m*m + 1e-5f);
        }
        __syncthreads();
        for (int i = tid; i < SS*DD; i += 256) {
            int s = i >> 6, d = i & 63;
            xb[i] = (upd[i]-m7[s])*r7[s]*lsg[d] + lsb[d];
        }
        __syncthreads();
        for (int o = tid; o < SS*DD; o += 256) {
            int s = o >> 6, d = o & 63;
            float acc = 0.f;
            for (int dp = 0; dp < DD; dp++) acc += xb[s*DD+dp]*g_P[dp*DD+d];
            g_qp[b*SS*DD+o] = 0.125f*acc;
            g_U[b*SS*DD+o] = 0.f;
        }
        if (tid < SS) g_Z[b*SS+tid] = 0.f;
    }
}

// ---------------------------------------------------------------------------
extern "C" void kernel_launch(void* const* d_in, const int* in_sizes, int n_in,
                              void* d_out, int out_size) {
    const float* inputs     = (const float*)d_in[0];
    const float* ln_in_g    = (const float*)d_in[1];
    const float* ln_in_b    = (const float*)d_in[2];
    const float* ln_slots_g = (const float*)d_in[3];
    const float* ln_slots_b = (const float*)d_in[4];
    const float* ln_mlp_g   = (const float*)d_in[5];
    const float* ln_mlp_b   = (const float*)d_in[6];
    const float* Wq         = (const float*)d_in[7];
    const float* Wk         = (const float*)d_in[8];
    const float* Wv         = (const float*)d_in[9];
    const float* mu         = (const float*)d_in[10];
    const float* lsig       = (const float*)d_in[11];
    const float* w_ih       = (const float*)d_in[12];
    const float* w_hh       = (const float*)d_in[13];
    const float* b_ih       = (const float*)d_in[14];
    const float* b_hh       = (const float*)d_in[15];
    const float* w1         = (const float*)d_in[16];
    const float* b1         = (const float*)d_in[17];
    const float* w2         = (const float*)d_in[18];
    const float* b2         = (const float*)d_in[19];
    const float* nslots     = (const float*)d_in[20];
    const float* nh         = (const float*)d_in[21];
    float* out = (float*)d_out;

    k_setup<<<BB+1, 256>>>(mu, lsig, nslots, nh, Wq, Wk);
    k_qp0<<<BB, 256>>>(ln_slots_g, ln_slots_b);
    for (int it = 0; it < 3; it++) {
        k_attn<<<BB*TILES_PER_B, TPB_ATTN>>>(inputs, ln_in_g, ln_in_b);
        k_update<<<BB, 256>>>(Wv, w_ih, w_hh, b_ih, b_hh, w1, b1, w2, b2,
                              ln_slots_g, ln_slots_b, ln_mlp_g, ln_mlp_b,
                              out, it == 2);
    }
}

// round 2
// speedup vs baseline: 2.3048x; 2.3048x over previous
#include <cuda_runtime.h>
#include <math.h>

#define BB 32
#define NN 16384
#define DD 64
#define SS 7
#define HH 128
#define TILE 256
#define TPB 256
#define TILES_PER_B (NN / TILE)   // 64

__device__ __align__(16) float g_P[DD*DD];
__device__ __align__(16) float g_slots[BB*SS*DD];
__device__ __align__(16) float g_h0[BB*DD];
__device__ __align__(16) float g_qp[BB*SS*DD];
__device__ __align__(16) float g_U[BB*SS*DD];
__device__ float g_Z[BB*SS];

// ---- k_attn dynamic smem layout (floats) ----
#define XN_PITCH   19                     // float4 units per row
#define OFF_XN     0                      // 256*19 f4 = 19456 floats
#define OFF_PART   19456                  // 4*7*16 f4 = 1792 floats
#define OFF_QP     21248                  // 112 f4 = 448 floats
#define OFF_PT     21696                  // 256*8 = 2048 floats
#define OFF_G      23744
#define OFF_B      23808
#define OFF_ZP     23872                  // 32
#define ATTN_SMEM_FLOATS 23904
#define ATTN_SMEM_BYTES (ATTN_SMEM_FLOATS*4)

// ---- k_update dynamic smem layout (floats) ----
#define UO_WHH 0                          // 192*65 = 12480
#define UO_W1  12480                      // 128*65 = 8320
#define UO_W2  20800                      // 64*129 = 8256
#define UO_GI  29056                      // 1344
#define UO_UPD 30400                      // 448
#define UO_SL  30848                      // 448
#define UO_XB  31296                      // 448
#define UO_SU  31744                      // 448
#define UO_HID 32192                      // 896
#define UO_H   33088                      // 64
#define UO_GH  33152                      // 192
#define UO_SZ  33344                      // 8
#define UO_M7  33352                      // 8
#define UO_R7  33360                      // 8
#define UPD_SMEM_FLOATS 33368
#define UPD_SMEM_BYTES (UPD_SMEM_FLOATS*4)

// ---------------------------------------------------------------------------
// k_setup: blocks 0..31 -> slots/h0 init + zero U,Z.  block 32 -> P = Wq^T Wk
// ---------------------------------------------------------------------------
__global__ void k_setup(const float* __restrict__ mu, const float* __restrict__ lsig,
                        const float* __restrict__ nslots, const float* __restrict__ nh,
                        const float* __restrict__ Wq, const float* __restrict__ Wk) {
    int blk = blockIdx.x, tid = threadIdx.x;
    if (blk < BB) {
        int b = blk;
        for (int i = tid; i < SS*DD; i += blockDim.x) {
            int d = i & (DD-1);
            float sg = expf(lsig[d]);
            g_slots[b*SS*DD + i] = mu[d] + sg * nslots[b*SS*DD + i];
            g_U[b*SS*DD + i] = 0.f;
        }
        for (int d = tid; d < DD; d += blockDim.x) {
            float sg = expf(lsig[d]);
            g_h0[b*DD + d] = mu[d] + sg * nh[b*DD + d];
        }
        if (tid < SS) g_Z[b*SS + tid] = 0.f;
    } else {
        __shared__ float sq[DD*DD], sk[DD*DD];
        for (int i = tid; i < DD*DD; i += blockDim.x) { sq[i] = Wq[i]; sk[i] = Wk[i]; }
        __syncthreads();
        for (int i = tid; i < DD*DD; i += blockDim.x) {
            int dp = i >> 6, d = i & 63;
            float acc = 0.f;
            for (int e = 0; e < DD; e++) acc += sq[e*DD+dp] * sk[e*DD+d];
            g_P[i] = acc;
        }
    }
}

// ---------------------------------------------------------------------------
// k_qp0: q'[b,s,:] = scale * LN_slots(slots[b,s]) @ P    (iteration-0 q')
// ---------------------------------------------------------------------------
__global__ void k_qp0(const float* __restrict__ lsg, const float* __restrict__ lsb) {
    int b = blockIdx.x, tid = threadIdx.x;
    __shared__ float sl[SS*DD], sn[SS*DD], m7[SS], r7[SS];
    for (int i = tid; i < SS*DD; i += blockDim.x) sl[i] = g_slots[b*SS*DD+i];
    __syncthreads();
    if (tid < SS) {
        float sm = 0.f, sq = 0.f;
        for (int d = 0; d < DD; d++) { float v = sl[tid*DD+d]; sm += v; sq += v*v; }
        float m = sm * (1.f/DD);
        m7[tid] = m;
        r7[tid] = rsqrtf(sq*(1.f/DD) - m*m + 1e-5f);
    }
    __syncthreads();
    for (int i = tid; i < SS*DD; i += blockDim.x) {
        int s = i >> 6, d = i & 63;
        sn[i] = (sl[i]-m7[s])*r7[s]*lsg[d] + lsb[d];
    }
    __syncthreads();
    for (int o = tid; o < SS*DD; o += blockDim.x) {
        int s = o >> 6, d = o & 63;
        float acc = 0.f;
        for (int dp = 0; dp < DD; dp++) acc += sn[s*DD+dp] * g_P[dp*DD+d];
        g_qp[b*SS*DD+o] = 0.125f * acc;
    }
}

// ---------------------------------------------------------------------------
// k_attn: fused LN -> logits -> softmax -> outer-product accumulation
// ---------------------------------------------------------------------------
__global__ __launch_bounds__(TPB, 2)
void k_attn(const float* __restrict__ x_in,
            const float* __restrict__ lg, const float* __restrict__ lb) {
    extern __shared__ __align__(16) float smem[];
    float4* s_xn   = (float4*)smem;                  // [256][19]
    float4* s_part = (float4*)(smem + OFF_PART);     // [4*7][16]
    float4* s_qp   = (float4*)(smem + OFF_QP);       // [7][16]
    float*  s_pT   = smem + OFF_PT;                  // [256][8]
    float*  s_g    = smem + OFF_G;
    float*  s_b    = smem + OFF_B;
    float*  s_z    = smem + OFF_ZP;                  // [7][4] as s*4+g

    int b   = blockIdx.x >> 6;
    int rb  = (blockIdx.x & (TILES_PER_B-1)) * TILE;
    int tid = threadIdx.x;

    for (int i = tid; i < SS*DD/4; i += TPB)
        s_qp[i] = ((const float4*)(g_qp + b*SS*DD))[i];
    if (tid < DD) { s_g[tid] = lg[tid]; s_b[tid] = lb[tid]; }
    __syncthreads();

    // ---- phase 1: one row per thread ----
    {
        const float4* xp = (const float4*)(x_in + ((long)b*NN + rb + tid)*DD);
        float4 x[16];
#pragma unroll
        for (int j = 0; j < 16; j++) x[j] = xp[j];
        float sm = 0.f, sq = 0.f;
#pragma unroll
        for (int j = 0; j < 16; j++) {
            sm += x[j].x + x[j].y + x[j].z + x[j].w;
            sq += x[j].x*x[j].x + x[j].y*x[j].y + x[j].z*x[j].z + x[j].w*x[j].w;
        }
        float m = sm * (1.f/DD);
        float rstd = rsqrtf(sq*(1.f/DD) - m*m + 1e-5f);
#pragma unroll
        for (int j = 0; j < 16; j++) {
            x[j].x = (x[j].x - m)*rstd*s_g[4*j+0] + s_b[4*j+0];
            x[j].y = (x[j].y - m)*rstd*s_g[4*j+1] + s_b[4*j+1];
            x[j].z = (x[j].z - m)*rstd*s_g[4*j+2] + s_b[4*j+2];
            x[j].w = (x[j].w - m)*rstd*s_g[4*j+3] + s_b[4*j+3];
        }
        float l[SS];
#pragma unroll
        for (int s = 0; s < SS; s++) {
            float acc = 0.f;
#pragma unroll
            for (int j = 0; j < 16; j++) {
                float4 q = s_qp[s*16+j];
                acc += x[j].x*q.x + x[j].y*q.y + x[j].z*q.z + x[j].w*q.w;
            }
            l[s] = acc;
        }
        float mx = l[0];
#pragma unroll
        for (int s = 1; s < SS; s++) mx = fmaxf(mx, l[s]);
        float es[SS], se = 0.f;
#pragma unroll
        for (int s = 0; s < SS; s++) { es[s] = __expf(l[s]-mx); se += es[s]; }
        float inv = 1.f/se;
#pragma unroll
        for (int s = 0; s < SS; s++) s_pT[tid*8+s] = es[s]*inv + 1e-8f;
#pragma unroll
        for (int j = 0; j < 16; j++) s_xn[tid*XN_PITCH+j] = x[j];
    }
    __syncthreads();

    // ---- phase 2a: per-row-group partial outer products ----
    if (tid < 64) {                                  // (g, dq): 4 groups x 16 quads
        int g = tid >> 4, dq = tid & 15;
        float4 a0={0,0,0,0},a1={0,0,0,0},a2={0,0,0,0},a3={0,0,0,0},
               a4={0,0,0,0},a5={0,0,0,0},a6={0,0,0,0};
        int r0 = g*64;
#pragma unroll 4
        for (int r = r0; r < r0+64; r++) {
            float4 xv = s_xn[r*XN_PITCH+dq];
            float4 pA = *(const float4*)&s_pT[r*8];
            float4 pB = *(const float4*)&s_pT[r*8+4];
            a0.x += pA.x*xv.x; a0.y += pA.x*xv.y; a0.z += pA.x*xv.z; a0.w += pA.x*xv.w;
            a1.x += pA.y*xv.x; a1.y += pA.y*xv.y; a1.z += pA.y*xv.z; a1.w += pA.y*xv.w;
            a2.x += pA.z*xv.x; a2.y += pA.z*xv.y; a2.z += pA.z*xv.z; a2.w += pA.z*xv.w;
            a3.x += pA.w*xv.x; a3.y += pA.w*xv.y; a3.z += pA.w*xv.z; a3.w += pA.w*xv.w;
            a4.x += pB.x*xv.x; a4.y += pB.x*xv.y; a4.z += pB.x*xv.z; a4.w += pB.x*xv.w;
            a5.x += pB.y*xv.x; a5.y += pB.y*xv.y; a5.z += pB.y*xv.z; a5.w += pB.y*xv.w;
            a6.x += pB.z*xv.x; a6.y += pB.z*xv.y; a6.z += pB.z*xv.z; a6.w += pB.z*xv.w;
        }
        s_part[(g*SS+0)*16+dq] = a0; s_part[(g*SS+1)*16+dq] = a1;
        s_part[(g*SS+2)*16+dq] = a2; s_part[(g*SS+3)*16+dq] = a3;
        s_part[(g*SS+4)*16+dq] = a4; s_part[(g*SS+5)*16+dq] = a5;
        s_part[(g*SS+6)*16+dq] = a6;
    } else if (tid < 64+28) {                        // Z partials
        int t = tid-64, s = t >> 2, g = t & 3;
        float z = 0.f;
        int r0 = g*64;
#pragma unroll 4
        for (int r = r0; r < r0+64; r++) z += s_pT[r*8+s];
        s_z[s*4+g] = z;
    }
    __syncthreads();

    // ---- phase 2b: merge partials, one RED per output ----
    if (tid < SS*16) {
        int s = tid >> 4, dq = tid & 15;
        float4 p0 = s_part[(0*SS+s)*16+dq], p1 = s_part[(1*SS+s)*16+dq];
        float4 p2 = s_part[(2*SS+s)*16+dq], p3 = s_part[(3*SS+s)*16+dq];
        float4 r;
        r.x = p0.x+p1.x+p2.x+p3.x; r.y = p0.y+p1.y+p2.y+p3.y;
        r.z = p0.z+p1.z+p2.z+p3.z; r.w = p0.w+p1.w+p2.w+p3.w;
        float* up = g_U + (b*SS + s)*DD + dq*4;
        atomicAdd(up+0, r.x); atomicAdd(up+1, r.y);
        atomicAdd(up+2, r.z); atomicAdd(up+3, r.w);
    } else if (tid < SS*16 + SS) {
        int s = tid - SS*16;
        atomicAdd(&g_Z[b*SS+s], s_z[s*4+0]+s_z[s*4+1]+s_z[s*4+2]+s_z[s*4+3]);
    }
}

// ---------------------------------------------------------------------------
// k_update: updates -> GRU -> MLP -> slots + next q'  (weights staged in smem)
// ---------------------------------------------------------------------------
__global__ __launch_bounds__(256)
void k_update(const float* __restrict__ Wv,
              const float* __restrict__ w_ih, const float* __restrict__ w_hh,
              const float* __restrict__ b_ih, const float* __restrict__ b_hh,
              const float* __restrict__ w1, const float* __restrict__ b1,
              const float* __restrict__ w2, const float* __restrict__ b2,
              const float* __restrict__ lsg, const float* __restrict__ lsb,
              const float* __restrict__ lmg, const float* __restrict__ lmb,
              float* __restrict__ dout, int last) {
    extern __shared__ __align__(16) float sm[];
    float* whh = sm + UO_WHH;    // [192][65]
    float* w1s = sm + UO_W1;     // [128][65]
    float* w2s = sm + UO_W2;     // [64][129]
    float* gi  = sm + UO_GI;     // [7][192]
    float* upd = sm + UO_UPD;    // [7][64]
    float* sl  = sm + UO_SL;
    float* xb  = sm + UO_XB;
    float* sU  = sm + UO_SU;
    float* hid = sm + UO_HID;    // [7][128]
    float* h   = sm + UO_H;
    float* ghs = sm + UO_GH;     // [192]
    float* sZ  = sm + UO_SZ;
    float* m7  = sm + UO_M7;
    float* r7  = sm + UO_R7;

    int b = blockIdx.x, tid = threadIdx.x;

    // stage weights (bank-conflict-free pitches) + load state
    for (int i = tid; i < 3*DD*DD; i += 256) { int r = i>>6, e = i&63; whh[r*65+e] = w_hh[i]; }
    for (int i = tid; i < HH*DD;   i += 256) { int r = i>>6, e = i&63; w1s[r*65+e] = w1[i]; }
    for (int i = tid; i < DD*HH;   i += 256) { int r = i>>7, k = i&127; w2s[r*129+k] = w2[i]; }
    for (int i = tid; i < SS*DD;   i += 256) sU[i] = g_U[b*SS*DD+i];
    if (tid < SS) sZ[tid] = g_Z[b*SS+tid];
    if (tid < DD) h[tid] = g_h0[b*DD+tid];
    __syncthreads();

    // updates[s][e] = (U[s] . Wv[e]) / Z[s]
    for (int o = tid; o < SS*DD; o += 256) {
        int s = o >> 6, e = o & 63;
        const float4* w = (const float4*)(Wv + e*DD);
        const float4* u = (const float4*)(sU + s*DD);
        float acc = 0.f;
#pragma unroll
        for (int j = 0; j < 16; j++) {
            float4 a = u[j], c = w[j];
            acc += a.x*c.x + a.y*c.y + a.z*c.z + a.w*c.w;
        }
        upd[o] = acc / sZ[s];
    }
    __syncthreads();

    // gi for ALL slots in parallel (h-independent)
    for (int o = tid; o < SS*3*DD; o += 256) {
        int s = o / (3*DD), go = o % (3*DD);
        const float4* w = (const float4*)(w_ih + go*DD);
        const float4* u = (const float4*)(upd + s*DD);
        float acc = b_ih[go];
#pragma unroll
        for (int j = 0; j < 16; j++) {
            float4 a = u[j], c = w[j];
            acc += a.x*c.x + a.y*c.y + a.z*c.z + a.w*c.w;
        }
        gi[s*3*DD+go] = acc;
    }
    __syncthreads();

    // GRU over slot axis, smem-resident
    for (int s = 0; s < SS; s++) {
        if (tid < 3*DD) {
            float c = b_hh[tid];
            const float* w = whh + tid*65;
#pragma unroll 16
            for (int e = 0; e < DD; e++) c += h[e]*w[e];
            ghs[tid] = c;
        }
        __syncthreads();
        if (tid < DD) {
            float r = 1.f/(1.f + __expf(-(gi[s*192+tid]     + ghs[tid])));
            float z = 1.f/(1.f + __expf(-(gi[s*192+64+tid]  + ghs[64+tid])));
            float n = tanhf(gi[s*192+128+tid] + r*ghs[128+tid]);
            float hn = (1.f-z)*n + z*h[tid];
            h[tid] = hn;            // safe: each thread touches only h[tid]
            sl[s*DD+tid] = hn;
        }
        __syncthreads();
    }

    // MLP: slots += relu(LN_mlp(slots) @ w1^T + b1) @ w2^T + b2
    if (tid < SS) {
        float smv = 0.f, sq = 0.f;
        for (int d = 0; d < DD; d++) { float v = sl[tid*DD+d]; smv += v; sq += v*v; }
        float m = smv*(1.f/DD);
        m7[tid] = m; r7[tid] = rsqrtf(sq*(1.f/DD) - m*m + 1e-5f);
    }
    __syncthreads();
    for (int i = tid; i < SS*DD; i += 256) {
        int s = i >> 6, d = i & 63;
        xb[i] = (sl[i]-m7[s])*r7[s]*lmg[d] + lmb[d];
    }
    __syncthreads();
    for (int o = tid; o < SS*HH; o += 256) {
        int s = o >> 7, hc = o & 127;
        float acc = b1[hc];
        const float* w = w1s + hc*65;
#pragma unroll 16
        for (int d = 0; d < DD; d++) acc += xb[s*DD+d]*w[d];
        hid[o] = fmaxf(acc, 0.f);
    }
    __syncthreads();
    for (int o = tid; o < SS*DD; o += 256) {
        int s = o >> 6, d = o & 63;
        float acc = b2[d];
        const float* w = w2s + d*129;
#pragma unroll 16
        for (int k = 0; k < HH; k++) acc += hid[s*HH+k]*w[k];
        float v = sl[o] + acc;
        upd[o] = v;                     // reuse as new-slots buffer
        g_slots[b*SS*DD+o] = v;
        dout[b*SS*DD+o] = v;
    }
    __syncthreads();

    if (!last) {
        if (tid < SS) {
            float smv = 0.f, sq = 0.f;
            for (int d = 0; d < DD; d++) { float v = upd[tid*DD+d]; smv += v; sq += v*v; }
            float m = smv*(1.f/DD);
            m7[tid] = m; r7[tid] = rsqrtf(sq*(1.f/DD) - m*m + 1e-5f);
        }
        __syncthreads();
        for (int i = tid; i < SS*DD; i += 256) {
            int s = i >> 6, d = i & 63;
            xb[i] = (upd[i]-m7[s])*r7[s]*lsg[d] + lsb[d];
        }
        __syncthreads();
        for (int o = tid; o < SS*DD; o += 256) {
            int s = o >> 6, d = o & 63;
            float acc = 0.f;
            for (int dp = 0; dp < DD; dp++) acc += xb[s*DD+dp]*g_P[dp*DD+d];
            g_qp[b*SS*DD+o] = 0.125f*acc;
            g_U[b*SS*DD+o] = 0.f;
        }
        if (tid < SS) g_Z[b*SS+tid] = 0.f;
    }
}

// ---------------------------------------------------------------------------
extern "C" void kernel_launch(void* const* d_in, const int* in_sizes, int n_in,
                              void* d_out, int out_size) {
    const float* inputs     = (const float*)d_in[0];
    const float* ln_in_g    = (const float*)d_in[1];
    const float* ln_in_b    = (const float*)d_in[2];
    const float* ln_slots_g = (const float*)d_in[3];
    const float* ln_slots_b = (const float*)d_in[4];
    const float* ln_mlp_g   = (const float*)d_in[5];
    const float* ln_mlp_b   = (const float*)d_in[6];
    const float* Wq         = (const float*)d_in[7];
    const float* Wk         = (const float*)d_in[8];
    const float* Wv         = (const float*)d_in[9];
    const float* mu         = (const float*)d_in[10];
    const float* lsig       = (const float*)d_in[11];
    const float* w_ih       = (const float*)d_in[12];
    const float* w_hh       = (const float*)d_in[13];
    const float* b_ih       = (const float*)d_in[14];
    const float* b_hh       = (const float*)d_in[15];
    const float* w1         = (const float*)d_in[16];
    const float* b1         = (const float*)d_in[17];
    const float* w2         = (const float*)d_in[18];
    const float* b2         = (const float*)d_in[19];
    const float* nslots     = (const float*)d_in[20];
    const float* nh         = (const float*)d_in[21];
    float* out = (float*)d_out;

    cudaFuncSetAttribute(k_attn,  cudaFuncAttributeMaxDynamicSharedMemorySize, ATTN_SMEM_BYTES);
    cudaFuncSetAttribute(k_update, cudaFuncAttributeMaxDynamicSharedMemorySize, UPD_SMEM_BYTES);

    k_setup<<<BB+1, 256>>>(mu, lsig, nslots, nh, Wq, Wk);
    k_qp0<<<BB, 256>>>(ln_slots_g, ln_slots_b);
    for (int it = 0; it < 3; it++) {
        k_attn<<<BB*TILES_PER_B, TPB, ATTN_SMEM_BYTES>>>(inputs, ln_in_g, ln_in_b);
        k_update<<<BB, 256, UPD_SMEM_BYTES>>>(Wv, w_ih, w_hh, b_ih, b_hh, w1, b1, w2, b2,
                                              ln_slots_g, ln_slots_b, ln_mlp_g, ln_mlp_b,
                                              out, it == 2);
    }
}

// round 4
// speedup vs baseline: 2.8902x; 1.2540x over previous
#include <cuda_runtime.h>
#include <cuda_fp16.h>
#include <math.h>

#define BB 32
#define NN 16384
#define DD 64
#define SS 7
#define HH 128
#define TILE 256
#define TPB 256
#define TILES_PER_B (NN / TILE)   // 64

__device__ __align__(16) float g_P[DD*DD];
__device__ __align__(16) float g_slots[BB*SS*DD];
__device__ __align__(16) float g_h0[BB*DD];
__device__ __align__(16) float g_qp[BB*SS*DD];
__device__ __align__(16) float g_U[BB*SS*DD];
__device__ float g_Z[BB*SS];
__device__ __align__(16) __half g_xn[(long)BB*NN*DD];   // 64 MB LN(x) cache

// ---- k_attn smem layout (floats) ----
#define OFF_XN   0        // 256 rows * 9 f4 (fp16 data) = 9216 fl
#define OFF_PT   9216     // 256*8
#define OFF_QP   11264    // 112 f4 = 448 fl
#define OFF_PART 11712    // 16 groups * 7 * 64 = 7168 fl
#define OFF_Z    18880    // 112
#define ATTN_SMEM_BYTES ((18992)*4)

// ---- k_prep smem layout (floats) ----
#define P_IN  0           // 128 rows * 17 f4 = 8704 fl
#define P_OUT 8704        // 128 rows * 9 f4  = 4608 fl
#define P_G   13312
#define P_B   13376
#define PREP_SMEM_BYTES ((13440)*4)

// ---- k_update smem layout (floats) ----
#define UO_WHH 0          // 192*68 = 13056
#define UO_GI  13056      // 1344
#define UO_UPD 14400      // 448
#define UO_SL  14848      // 448
#define UO_XB  15296      // 448
#define UO_SU  15744      // 448
#define UO_HID 16192      // 896
#define UO_H   17088      // 64
#define UO_GH  17152      // 192
#define UO_SZ  17344
#define UO_M7  17352
#define UO_R7  17360
#define UPD_SMEM_BYTES ((17368)*4)

__device__ __forceinline__ void h8_to_f(const uint4& v, float* f) {
    const __half2* h = (const __half2*)&v;
    float2 t;
    t = __half22float2(h[0]); f[0]=t.x; f[1]=t.y;
    t = __half22float2(h[1]); f[2]=t.x; f[3]=t.y;
    t = __half22float2(h[2]); f[4]=t.x; f[5]=t.y;
    t = __half22float2(h[3]); f[6]=t.x; f[7]=t.y;
}

__device__ __forceinline__ unsigned pack_h2(float a, float b) {
    __half2 h = __float22half2_rn(make_float2(a, b));
    return *(unsigned*)&h;
}

// ---------------------------------------------------------------------------
// k_setup: blocks 0..31 -> slots/h0 init + zero U,Z.  block 32 -> P = Wq^T Wk
// ---------------------------------------------------------------------------
__global__ void k_setup(const float* __restrict__ mu, const float* __restrict__ lsig,
                        const float* __restrict__ nslots, const float* __restrict__ nh,
                        const float* __restrict__ Wq, const float* __restrict__ Wk) {
    int blk = blockIdx.x, tid = threadIdx.x;
    if (blk < BB) {
        int b = blk;
        for (int i = tid; i < SS*DD; i += blockDim.x) {
            int d = i & (DD-1);
            float sg = __expf(lsig[d]);
            g_slots[b*SS*DD + i] = mu[d] + sg * nslots[b*SS*DD + i];
            g_U[b*SS*DD + i] = 0.f;
        }
        for (int d = tid; d < DD; d += blockDim.x) {
            float sg = __expf(lsig[d]);
            g_h0[b*DD + d] = mu[d] + sg * nh[b*DD + d];
        }
        if (tid < SS) g_Z[b*SS + tid] = 0.f;
    } else {
        __shared__ float sq[DD*DD], sk[DD*DD];
        for (int i = tid; i < DD*DD; i += blockDim.x) { sq[i] = Wq[i]; sk[i] = Wk[i]; }
        __syncthreads();
        for (int i = tid; i < DD*DD; i += blockDim.x) {
            int dp = i >> 6, d = i & 63;
            float acc = 0.f;
            for (int e = 0; e < DD; e++) acc += sq[e*DD+dp] * sk[e*DD+d];
            g_P[i] = acc;
        }
    }
}

// ---------------------------------------------------------------------------
// k_prep: LN(inputs) -> g_xn (fp16), coalesced in & out via smem bounce
// ---------------------------------------------------------------------------
__global__ __launch_bounds__(256)
void k_prep(const float* __restrict__ x_in,
            const float* __restrict__ lg, const float* __restrict__ lb) {
    extern __shared__ __align__(16) float sp[];
    float4* s_in  = (float4*)(sp + P_IN);      // [128][17]
    uint4*  s_out = (uint4*)(sp + P_OUT);      // [128][9]
    float*  s_g   = sp + P_G;
    float*  s_b   = sp + P_B;
    int tid = threadIdx.x;
    long row_base = (long)blockIdx.x * 128;

    if (tid < DD) { s_g[tid] = lg[tid]; s_b[tid] = lb[tid]; }
    const float4* gin = (const float4*)x_in + row_base*16;
#pragma unroll
    for (int jj = 0; jj < 8; jj++) {
        int li = jj*256 + tid;
        s_in[(li>>4)*17 + (li&15)] = gin[li];
    }
    __syncthreads();

    if (tid < 128) {
        const float4* xr = s_in + tid*17;
        float4 x[16];
#pragma unroll
        for (int j = 0; j < 16; j++) x[j] = xr[j];
        float sm = 0.f, sq = 0.f;
#pragma unroll
        for (int j = 0; j < 16; j++) {
            sm += x[j].x + x[j].y + x[j].z + x[j].w;
            sq += x[j].x*x[j].x + x[j].y*x[j].y + x[j].z*x[j].z + x[j].w*x[j].w;
        }
        float m = sm * (1.f/DD);
        float rstd = rsqrtf(sq*(1.f/DD) - m*m + 1e-5f);
#pragma unroll
        for (int j = 0; j < 8; j++) {
            float4 a = x[2*j], c = x[2*j+1];
            float n0 = (a.x-m)*rstd*s_g[8*j+0] + s_b[8*j+0];
            float n1 = (a.y-m)*rstd*s_g[8*j+1] + s_b[8*j+1];
            float n2 = (a.z-m)*rstd*s_g[8*j+2] + s_b[8*j+2];
            float n3 = (a.w-m)*rstd*s_g[8*j+3] + s_b[8*j+3];
            float n4 = (c.x-m)*rstd*s_g[8*j+4] + s_b[8*j+4];
            float n5 = (c.y-m)*rstd*s_g[8*j+5] + s_b[8*j+5];
            float n6 = (c.z-m)*rstd*s_g[8*j+6] + s_b[8*j+6];
            float n7 = (c.w-m)*rstd*s_g[8*j+7] + s_b[8*j+7];
            uint4 o;
            o.x = pack_h2(n0, n1);
            o.y = pack_h2(n2, n3);
            o.z = pack_h2(n4, n5);
            o.w = pack_h2(n6, n7);
            s_out[tid*9 + j] = o;
        }
    }
    __syncthreads();

    uint4* gout = (uint4*)g_xn + row_base*8;
#pragma unroll
    for (int jj = 0; jj < 4; jj++) {
        int li = jj*256 + tid;
        gout[li] = s_out[(li>>3)*9 + (li&7)];
    }
}

// ---------------------------------------------------------------------------
// k_qp0: q'[b,s,:] = scale * LN_slots(slots[b,s]) @ P
// ---------------------------------------------------------------------------
__global__ void k_qp0(const float* __restrict__ lsg, const float* __restrict__ lsb) {
    int b = blockIdx.x, tid = threadIdx.x;
    __shared__ float sl[SS*DD], sn[SS*DD], m7[SS], r7[SS];
    for (int i = tid; i < SS*DD; i += blockDim.x) sl[i] = g_slots[b*SS*DD+i];
    __syncthreads();
    if (tid < SS) {
        float sm = 0.f, sq = 0.f;
        for (int d = 0; d < DD; d++) { float v = sl[tid*DD+d]; sm += v; sq += v*v; }
        float m = sm * (1.f/DD);
        m7[tid] = m;
        r7[tid] = rsqrtf(sq*(1.f/DD) - m*m + 1e-5f);
    }
    __syncthreads();
    for (int i = tid; i < SS*DD; i += blockDim.x) {
        int s = i >> 6, d = i & 63;
        sn[i] = (sl[i]-m7[s])*r7[s]*lsg[d] + lsb[d];
    }
    __syncthreads();
    for (int o = tid; o < SS*DD; o += blockDim.x) {
        int s = o >> 6, d = o & 63;
        float acc = 0.f;
        for (int dp = 0; dp < DD; dp++) acc += sn[s*DD+dp] * g_P[dp*DD+d];
        g_qp[b*SS*DD+o] = 0.125f * acc;
    }
}

// ---------------------------------------------------------------------------
// k_attn: logits from fp16 xn cache -> softmax -> outer-product accumulate
// ---------------------------------------------------------------------------
__global__ __launch_bounds__(TPB, 3)
void k_attn() {
    extern __shared__ __align__(16) float smem[];
    uint4*  s_xn4 = (uint4*)(smem + OFF_XN);     // [256][9] (fp16 rows)
    float*  s_pT  = smem + OFF_PT;               // [256][8]
    float4* s_pT4 = (float4*)s_pT;
    float4* s_qp4 = (float4*)(smem + OFF_QP);    // [7][16]
    float*  s_part= smem + OFF_PART;             // [16][7][64]
    float4* s_part4 = (float4*)s_part;
    float*  s_z   = smem + OFF_Z;                // [7][16]

    int b   = blockIdx.x >> 6;
    int rb  = (blockIdx.x & (TILES_PER_B-1)) * TILE;
    int tid = threadIdx.x;

    // phase 0: coalesced tile copy + q' load
    {
        const uint4* gx = (const uint4*)g_xn + ((long)b*NN + rb)*8;
#pragma unroll
        for (int jj = 0; jj < 8; jj++) {
            int li = jj*256 + tid;
            s_xn4[(li>>3)*9 + (li&7)] = gx[li];
        }
        for (int i = tid; i < SS*DD/4; i += TPB)
            s_qp4[i] = ((const float4*)(g_qp + b*SS*DD))[i];
    }
    __syncthreads();

    // phase 1: one row per thread -> logits -> softmax -> probs
    {
        const uint4* xr = s_xn4 + tid*9;
        float acc[SS];
#pragma unroll
        for (int s = 0; s < SS; s++) acc[s] = 0.f;
#pragma unroll
        for (int j = 0; j < 8; j++) {
            uint4 xv = xr[j];
            float xf[8]; h8_to_f(xv, xf);
#pragma unroll
            for (int s = 0; s < SS; s++) {
                float4 qa = s_qp4[s*16 + 2*j];
                float4 qb = s_qp4[s*16 + 2*j + 1];
                acc[s] += xf[0]*qa.x + xf[1]*qa.y + xf[2]*qa.z + xf[3]*qa.w
                        + xf[4]*qb.x + xf[5]*qb.y + xf[6]*qb.z + xf[7]*qb.w;
            }
        }
        float mx = acc[0];
#pragma unroll
        for (int s = 1; s < SS; s++) mx = fmaxf(mx, acc[s]);
        float es[SS], se = 0.f;
#pragma unroll
        for (int s = 0; s < SS; s++) { es[s] = __expf(acc[s]-mx); se += es[s]; }
        float inv = 1.f/se;
        s_pT4[tid*2]   = make_float4(es[0]*inv+1e-8f, es[1]*inv+1e-8f,
                                     es[2]*inv+1e-8f, es[3]*inv+1e-8f);
        s_pT4[tid*2+1] = make_float4(es[4]*inv+1e-8f, es[5]*inv+1e-8f,
                                     es[6]*inv+1e-8f, 0.f);
    }
    __syncthreads();

    // phase 2a: 16 row-groups x 8 d-chunks partial outer products
    if (tid < 128) {
        int g = tid >> 3, dc = tid & 7;
        int r0 = g*16;
        float a[SS][8];
#pragma unroll
        for (int s = 0; s < SS; s++)
#pragma unroll
            for (int k = 0; k < 8; k++) a[s][k] = 0.f;
#pragma unroll 4
        for (int rr = 0; rr < 16; rr++) {
            int r = r0 + rr;
            uint4 xv = s_xn4[r*9 + dc];
            float xf[8]; h8_to_f(xv, xf);
            float4 pA = s_pT4[r*2], pB = s_pT4[r*2+1];
            float p[SS] = {pA.x, pA.y, pA.z, pA.w, pB.x, pB.y, pB.z};
#pragma unroll
            for (int s = 0; s < SS; s++)
#pragma unroll
                for (int k = 0; k < 8; k++) a[s][k] += p[s]*xf[k];
        }
#pragma unroll
        for (int s = 0; s < SS; s++) {
            float* dst = s_part + (g*SS + s)*64 + dc*8;
            *(float4*)dst     = make_float4(a[s][0],a[s][1],a[s][2],a[s][3]);
            *(float4*)(dst+4) = make_float4(a[s][4],a[s][5],a[s][6],a[s][7]);
        }
    } else if (tid < 128 + 112) {                // Z partials
        int t = tid - 128, s = t >> 4, g = t & 15;
        float z = 0.f;
#pragma unroll 4
        for (int rr = 0; rr < 16; rr++) z += s_pT[(g*16+rr)*8 + s];
        s_z[s*16 + g] = z;
    }
    __syncthreads();

    // phase 2b: merge partials, one RED per output
    if (tid < SS*16) {
        int s = tid >> 4, dq = tid & 15;
        float4 r = make_float4(0.f,0.f,0.f,0.f);
#pragma unroll
        for (int g = 0; g < 16; g++) {
            float4 p = s_part4[(g*SS+s)*16 + dq];
            r.x += p.x; r.y += p.y; r.z += p.z; r.w += p.w;
        }
        float* up = g_U + (b*SS + s)*DD + dq*4;
        atomicAdd(up+0, r.x); atomicAdd(up+1, r.y);
        atomicAdd(up+2, r.z); atomicAdd(up+3, r.w);
    } else if (tid < SS*16 + SS) {
        int s = tid - SS*16;
        float z = 0.f;
#pragma unroll
        for (int g = 0; g < 16; g++) z += s_z[s*16+g];
        atomicAdd(&g_Z[b*SS+s], z);
    }
}

// ---------------------------------------------------------------------------
// k_update: updates -> GRU -> MLP -> slots + next q'
// ---------------------------------------------------------------------------
__global__ __launch_bounds__(256)
void k_update(const float* __restrict__ Wv,
              const float* __restrict__ w_ih, const float* __restrict__ w_hh,
              const float* __restrict__ b_ih, const float* __restrict__ b_hh,
              const float* __restrict__ w1, const float* __restrict__ b1,
              const float* __restrict__ w2, const float* __restrict__ b2,
              const float* __restrict__ lsg, const float* __restrict__ lsb,
              const float* __restrict__ lmg, const float* __restrict__ lmb,
              float* __restrict__ dout, int last) {
    extern __shared__ __align__(16) float sm[];
    float* whh = sm + UO_WHH;    // [192][68]
    float* gi  = sm + UO_GI;     // [7][192]
    float* upd = sm + UO_UPD;    // [7][64]
    float* sl  = sm + UO_SL;
    float* xb  = sm + UO_XB;
    float* sU  = sm + UO_SU;
    float* hid = sm + UO_HID;    // [7][128]
    float* h   = sm + UO_H;
    float* ghs = sm + UO_GH;     // [192]
    float* sZ  = sm + UO_SZ;
    float* m7  = sm + UO_M7;
    float* r7  = sm + UO_R7;

    int b = blockIdx.x, tid = threadIdx.x;

    for (int i = tid; i < 3*DD*DD; i += 256) { int r = i>>6, e = i&63; whh[r*68+e] = w_hh[i]; }
    for (int i = tid; i < SS*DD;   i += 256) sU[i] = g_U[b*SS*DD+i];
    if (tid < SS) sZ[tid] = g_Z[b*SS+tid];
    if (tid < DD) h[tid] = g_h0[b*DD+tid];
    __syncthreads();

    // updates[s][e] = (U[s] . Wv[e]) / Z[s]
    for (int o = tid; o < SS*DD; o += 256) {
        int s = o >> 6, e = o & 63;
        const float4* w = (const float4*)(Wv + e*DD);
        const float4* u = (const float4*)(sU + s*DD);
        float a0=0,a1=0,a2=0,a3=0;
#pragma unroll
        for (int j = 0; j < 16; j++) {
            float4 a = u[j], c = w[j];
            a0 += a.x*c.x; a1 += a.y*c.y; a2 += a.z*c.z; a3 += a.w*c.w;
        }
        upd[o] = ((a0+a1)+(a2+a3)) / sZ[s];
    }
    __syncthreads();

    // gi for all slots in parallel
    for (int o = tid; o < SS*3*DD; o += 256) {
        int s = o / (3*DD), go = o - s*(3*DD);
        const float4* w = (const float4*)(w_ih + go*DD);
        const float4* u = (const float4*)(upd + s*DD);
        float a0=b_ih[go],a1=0,a2=0,a3=0;
#pragma unroll
        for (int j = 0; j < 16; j++) {
            float4 a = u[j], c = w[j];
            a0 += a.x*c.x; a1 += a.y*c.y; a2 += a.z*c.z; a3 += a.w*c.w;
        }
        gi[s*3*DD+go] = (a0+a1)+(a2+a3);
    }
    __syncthreads();

    // GRU over slot axis
    for (int s = 0; s < SS; s++) {
        if (tid < 3*DD) {
            const float4* w = (const float4*)(whh + tid*68);
            const float4* hv = (const float4*)h;
            float a0=b_hh[tid],a1=0,a2=0,a3=0;
#pragma unroll
            for (int j = 0; j < 16; j++) {
                float4 c = w[j], a = hv[j];
                a0 += a.x*c.x; a1 += a.y*c.y; a2 += a.z*c.z; a3 += a.w*c.w;
            }
            ghs[tid] = (a0+a1)+(a2+a3);
        }
        __syncthreads();
        if (tid < DD) {
            float r = 1.f/(1.f + __expf(-(gi[s*192+tid]     + ghs[tid])));
            float z = 1.f/(1.f + __expf(-(gi[s*192+64+tid]  + ghs[64+tid])));
            float nx = gi[s*192+128+tid] + r*ghs[128+tid];
            float n = 1.f - 2.f/(__expf(2.f*nx) + 1.f);   // tanh
            float hn = (1.f-z)*n + z*h[tid];
            h[tid] = hn;
            sl[s*DD+tid] = hn;
        }
        __syncthreads();
    }

    // MLP: slots += relu(LN_mlp(slots) @ w1^T + b1) @ w2^T + b2
    if (tid < SS) {
        float smv = 0.f, sq = 0.f;
        for (int d = 0; d < DD; d++) { float v = sl[tid*DD+d]; smv += v; sq += v*v; }
        float m = smv*(1.f/DD);
        m7[tid] = m; r7[tid] = rsqrtf(sq*(1.f/DD) - m*m + 1e-5f);
    }
    __syncthreads();
    for (int i = tid; i < SS*DD; i += 256) {
        int s = i >> 6, d = i & 63;
        xb[i] = (sl[i]-m7[s])*r7[s]*lmg[d] + lmb[d];
    }
    __syncthreads();
    for (int o = tid; o < SS*HH; o += 256) {
        int s = o >> 7, hc = o & 127;
        const float4* w = (const float4*)(w1 + hc*DD);
        const float4* u = (const float4*)(xb + s*DD);
        float a0=b1[hc],a1=0,a2=0,a3=0;
#pragma unroll
        for (int j = 0; j < 16; j++) {
            float4 a = u[j], c = w[j];
            a0 += a.x*c.x; a1 += a.y*c.y; a2 += a.z*c.z; a3 += a.w*c.w;
        }
        hid[o] = fmaxf((a0+a1)+(a2+a3), 0.f);
    }
    __syncthreads();
    for (int o = tid; o < SS*DD; o += 256) {
        int s = o >> 6, d = o & 63;
        const float4* w = (const float4*)(w2 + d*HH);
        const float4* u = (const float4*)(hid + s*HH);
        float a0=b2[d],a1=0,a2=0,a3=0;
#pragma unroll
        for (int j = 0; j < 32; j++) {
            float4 a = u[j], c = w[j];
            a0 += a.x*c.x; a1 += a.y*c.y; a2 += a.z*c.z; a3 += a.w*c.w;
        }
        float v = sl[o] + (a0+a1)+(a2+a3);
        upd[o] = v;
        g_slots[b*SS*DD+o] = v;
        dout[b*SS*DD+o] = v;
    }
    __syncthreads();

    if (!last) {
        if (tid < SS) {
            float smv = 0.f, sq = 0.f;
            for (int d = 0; d < DD; d++) { float v = upd[tid*DD+d]; smv += v; sq += v*v; }
            float m = smv*(1.f/DD);
            m7[tid] = m; r7[tid] = rsqrtf(sq*(1.f/DD) - m*m + 1e-5f);
        }
        __syncthreads();
        for (int i = tid; i < SS*DD; i += 256) {
            int s = i >> 6, d = i & 63;
            xb[i] = (upd[i]-m7[s])*r7[s]*lsg[d] + lsb[d];
        }
        __syncthreads();
        for (int o = tid; o < SS*DD; o += 256) {
            int s = o >> 6, d = o & 63;
            float a0=0,a1=0,a2=0,a3=0;
#pragma unroll
            for (int dp = 0; dp < DD; dp += 4) {
                a0 += xb[s*DD+dp+0]*g_P[(dp+0)*DD+d];
                a1 += xb[s*DD+dp+1]*g_P[(dp+1)*DD+d];
                a2 += xb[s*DD+dp+2]*g_P[(dp+2)*DD+d];
                a3 += xb[s*DD+dp+3]*g_P[(dp+3)*DD+d];
            }
            g_qp[b*SS*DD+o] = 0.125f*((a0+a1)+(a2+a3));
            g_U[b*SS*DD+o] = 0.f;
        }
        if (tid < SS) g_Z[b*SS+tid] = 0.f;
    }
}

// ---------------------------------------------------------------------------
extern "C" void kernel_launch(void* const* d_in, const int* in_sizes, int n_in,
                              void* d_out, int out_size) {
    const float* inputs     = (const float*)d_in[0];
    const float* ln_in_g    = (const float*)d_in[1];
    const float* ln_in_b    = (const float*)d_in[2];
    const float* ln_slots_g = (const float*)d_in[3];
    const float* ln_slots_b = (const float*)d_in[4];
    const float* ln_mlp_g   = (const float*)d_in[5];
    const float* ln_mlp_b   = (const float*)d_in[6];
    const float* Wq         = (const float*)d_in[7];
    const float* Wk         = (const float*)d_in[8];
    const float* Wv         = (const float*)d_in[9];
    const float* mu         = (const float*)d_in[10];
    const float* lsig       = (const float*)d_in[11];
    const float* w_ih       = (const float*)d_in[12];
    const float* w_hh       = (const float*)d_in[13];
    const float* b_ih       = (const float*)d_in[14];
    const float* b_hh       = (const float*)d_in[15];
    const float* w1         = (const float*)d_in[16];
    const float* b1         = (const float*)d_in[17];
    const float* w2         = (const float*)d_in[18];
    const float* b2         = (const float*)d_in[19];
    const float* nslots     = (const float*)d_in[20];
    const float* nh         = (const float*)d_in[21];
    float* out = (float*)d_out;

    cudaFuncSetAttribute(k_prep,   cudaFuncAttributeMaxDynamicSharedMemorySize, PREP_SMEM_BYTES);
    cudaFuncSetAttribute(k_attn,   cudaFuncAttributeMaxDynamicSharedMemorySize, ATTN_SMEM_BYTES);
    cudaFuncSetAttribute(k_update, cudaFuncAttributeMaxDynamicSharedMemorySize, UPD_SMEM_BYTES);

    k_setup<<<BB+1, 256>>>(mu, lsig, nslots, nh, Wq, Wk);
    k_prep<<<(BB*NN)/128, 256, PREP_SMEM_BYTES>>>(inputs, ln_in_g, ln_in_b);
    k_qp0<<<BB, 256>>>(ln_slots_g, ln_slots_b);
    for (int it = 0; it < 3; it++) {
        k_attn<<<BB*TILES_PER_B, TPB, ATTN_SMEM_BYTES>>>();
        k_update<<<BB, 256, UPD_SMEM_BYTES>>>(Wv, w_ih, w_hh, b_ih, b_hh, w1, b1, w2, b2,
                                              ln_slots_g, ln_slots_b, ln_mlp_g, ln_mlp_b,
                                              out, it == 2);
    }
}